// round 10
// baseline (speedup 1.0000x reference)
#include <cuda_runtime.h>
#include <cstdint>

// Correlation layer: out[b, di*21+dj, h, w] = (1/64) * sum_c f1[b,c,h,w] * f2pad[b,c,h+di,w+dj]
// B=4, C=64, H=W=128, MAX_DISP=10, KS=21 (441 displacements), fp32.

#define B_      4
#define C_      64
#define H_      128
#define W_      128
#define KS_     21
#define PAD_    10

#define HB   2      // h rows per CTA
#define DIB  3      // di values per CTA
#define CC   8      // channels per chunk
#define NCHUNK (C_ / CC)   // 8
#define PW   152    // padded f2 row width
#define NROW (HB + DIB - 1)  // 4

#define F1_STRIDE (CC * W_ + 4)   // 1028 floats (4112 B ≡ 16 mod 128)
#define F2_STRIDE (CC * PW + 4)   // 1220 floats (4880 B ≡ 16 mod 128)
#define SMEM_F1   (HB * F1_STRIDE)        // 2056 floats
#define F2_USED   (NROW * F2_STRIDE)      // 4880 floats
#define F2_COPY   (F2_USED + 12)          // 4892; copy1-copy0 = 19568 B ≡ 112 mod 128
                                          // (odd multiple of 16 -> conflict-free djp split)
#define BUF_FLOATS (SMEM_F1 + 2 * F2_COPY) // 11840 floats
#define SMEM_BYTES (2 * BUF_FLOATS * 4)    // 94720 B per CTA (2 CTAs/SM)

#define NTHREADS 192   // 6 warps = 2 hl * 3 dil; lanes = 16 wg * 2 djp

// ---------------- cp.async helpers ----------------
__device__ __forceinline__ void cp_async16(float* smem_dst, const float* gsrc) {
    uint32_t s = (uint32_t)__cvta_generic_to_shared(smem_dst);
    asm volatile("cp.async.cg.shared.global [%0], [%1], 16;\n" :: "r"(s), "l"(gsrc));
}
__device__ __forceinline__ void cp_async8(float* smem_dst, const float* gsrc) {
    uint32_t s = (uint32_t)__cvta_generic_to_shared(smem_dst);
    asm volatile("cp.async.ca.shared.global [%0], [%1], 8;\n" :: "r"(s), "l"(gsrc));
}
__device__ __forceinline__ void cp_commit() {
    asm volatile("cp.async.commit_group;\n" ::: "memory");
}
template <int N>
__device__ __forceinline__ void cp_wait() {
    asm volatile("cp.async.wait_group %0;\n" :: "n"(N) : "memory");
}

// packed f32x2 fma: d = a*b + c on both 32-bit halves
__device__ __forceinline__ unsigned long long fma_x2(unsigned long long a,
                                                     unsigned long long b,
                                                     unsigned long long c) {
    unsigned long long d;
    asm("fma.rn.f32x2 %0, %1, %2, %3;" : "=l"(d) : "l"(a), "l"(b), "l"(c));
    return d;
}

// ---------------- inner compute ----------------
// Thread: dj = djp + 2k (k=0..10; k=10 junk for djp=1, never stored),
// w in [w0, w0+8). f2p points at copy_djp; copy1 is c0 shifted by one float,
// so both parities read identical even packed offsets: fb2[k+p].
__device__ __forceinline__ void compute_chunk(const float* __restrict__ f1p,
                                              const float* __restrict__ f2p,
                                              unsigned long long (&acc)[11][4]) {
#pragma unroll
    for (int c = 0; c < CC; c++) {
        const ulonglong2* f1v = reinterpret_cast<const ulonglong2*>(f1p + c * W_);
        const ulonglong2* f2v = reinterpret_cast<const ulonglong2*>(f2p + c * PW);
        unsigned long long fa2[4];
        unsigned long long fb2[14];
#pragma unroll
        for (int i = 0; i < 2; i++) {
            ulonglong2 t = f1v[i];
            fa2[2 * i] = t.x; fa2[2 * i + 1] = t.y;
        }
#pragma unroll
        for (int i = 0; i < 7; i++) {
            ulonglong2 t = f2v[i];
            fb2[2 * i] = t.x; fb2[2 * i + 1] = t.y;
        }
#pragma unroll
        for (int k = 0; k < 11; k++) {
#pragma unroll
            for (int p = 0; p < 4; p++)
                acc[k][p] = fma_x2(fa2[p], fb2[k + p], acc[k][p]);
        }
    }
}

// ---------------- staging (cp.async, gmem -> smem) ----------------
// f1: HB x CC x 128 floats via 16B. c0: interior x in [10,138) via 8B.
// copy1 is built in smem afterwards (never staged from gmem).
// 192 ≡ 0 mod 64: per-thread x components are loop-invariant.
__device__ __forceinline__ void stage_chunk(const float* __restrict__ f1base,
                                            const float* __restrict__ f2base,
                                            float* buf,
                                            int rlo, int nrows, int tid) {
    // ---- f1: items i = hc*32 + w4, hc = h*8 + c, 512 total ----
    {
        const int w4 = tid & 31;                // invariant
        int hc = tid >> 5;                      // advances by 6
        float* f1b = buf + w4 * 4;
        const float* src0 = f1base + w4 * 4;
#pragma unroll
        for (int j = 0; j < 3; j++) {
            if (hc < HB * CC) {
                int h = hc >> 3, c = hc & 7;
                cp_async16(f1b + h * F1_STRIDE + c * W_,
                           src0 + c * (H_ * W_) + h * W_);
            }
            hc += 6;
        }
    }
    // ---- c0: items i = (r*8 + c)*64 + x2, nrows*512 total ----
    {
        const int x2 = tid & 63;                // invariant
        int rc = tid >> 6;                      // r*8 + c, advances by 3
        const int rcmax = nrows * 8;
        float* c0 = buf + SMEM_F1 + rlo * F2_STRIDE + PAD_ + x2 * 2;
        const float* src0 = f2base + rlo * W_ + x2 * 2;
#pragma unroll
        for (int j = 0; j < 11; j++) {
            if (rc < rcmax) {
                int r = rc >> 3, c = rc & 7;
                cp_async8(c0 + r * F2_STRIDE + c * PW,
                          src0 + c * (H_ * W_) + r * W_);
            }
            rc += 3;
        }
    }
}

// ---------------- copy1 build (smem -> smem 1-float shift) ----------------
// copy1[i] = c0[i+1]; covers all of F2_USED (tail read stays in zero padding).
__device__ __forceinline__ void build_copy1(float* buf, int tid) {
    const float* c0 = buf + SMEM_F1;
    float* c1 = buf + SMEM_F1 + F2_COPY;
#pragma unroll
    for (int j = 0; j < (F2_USED / 4 + NTHREADS - 1) / NTHREADS; j++) {  // 7 iters
        int i4 = (tid + j * NTHREADS) * 4;
        if (i4 < F2_USED) {
            float4 v = *reinterpret_cast<const float4*>(c0 + i4);
            float nxt = c0[i4 + 4];
            *reinterpret_cast<float4*>(c1 + i4) = make_float4(v.y, v.z, v.w, nxt);
        }
    }
}

extern __shared__ float smem[];

__global__ __launch_bounds__(NTHREADS, 2)
void corr_kernel(const float* __restrict__ f1g,
                 const float* __restrict__ f2g,
                 float* __restrict__ out) {
    const int tid  = threadIdx.x;
    const int warp = tid >> 5;
    const int lane = tid & 31;
    const int hl   = warp & 1;      // h row (warp-uniform), HB=2
    const int dil  = warp >> 1;     // local di (warp-uniform), 0..2
    const int wg   = lane >> 1;     // w tile: w0 = wg*8
    const int djp  = lane & 1;      // dj parity
    const int w0   = wg * 8;

    const int b   = blockIdx.z;
    const int h0  = blockIdx.y * HB;
    const int di0 = blockIdx.x * DIB;
    const int r0  = h0 + di0 - PAD_;

    int rlo = (r0 < 0) ? -r0 : 0;
    int rhi = (r0 + NROW > H_) ? (H_ - r0) : NROW;
    if (rhi < rlo) { rlo = 0; rhi = 0; }
    const int nrows = rhi - rlo;

    float* buf0 = smem;
    float* buf1 = smem + BUF_FLOATS;

    // one-time zero of both f2 double-copies (padding/OOB stays zero forever)
    {
        float4 z = make_float4(0.f, 0.f, 0.f, 0.f);
        float4* z0 = reinterpret_cast<float4*>(buf0 + SMEM_F1);
        float4* z1 = reinterpret_cast<float4*>(buf1 + SMEM_F1);
        for (int i = tid; i < 2 * F2_COPY / 4; i += NTHREADS) { z0[i] = z; z1[i] = z; }
    }
    __syncthreads();

    // hoisted gmem bases (chunk stride is a constant add)
    const float* f1base = f1g + ((size_t)b * C_ * H_ + h0) * W_;
    const float* f2base = f2g + ((size_t)b * C_ * H_ + r0) * W_;
    const int chunk_gstride = CC * H_ * W_;

    stage_chunk(f1base, f2base, buf0, rlo, nrows, tid);
    cp_commit();
    stage_chunk(f1base + chunk_gstride, f2base + chunk_gstride, buf1, rlo, nrows, tid);
    cp_commit();

    // prologue: chunk 0 staged -> build its copy1
    cp_wait<1>();
    __syncthreads();          // c0[0] visible to all
    build_copy1(buf0, tid);   // c1[0]; visibility covered by sync #1 of iter 0

    unsigned long long acc[11][4];
#pragma unroll
    for (int k = 0; k < 11; k++)
#pragma unroll
        for (int p = 0; p < 4; p++) acc[k][p] = 0ull;

    const int f1off = hl * F1_STRIDE + w0;
    const int f2off = SMEM_F1 + djp * F2_COPY + (hl + dil) * F2_STRIDE + w0;

    for (int cc = 0; cc < NCHUNK; cc++) {
        float* buf  = (cc & 1) ? buf1 : buf0;
        float* nbuf = (cc & 1) ? buf0 : buf1;

        if (cc < NCHUNK - 1) cp_wait<0>();   // all staged groups (incl cc+1) done
        __syncthreads();                     // c0[cc+1] + c1[cc] visible to all

        if (cc + 1 < NCHUNK) build_copy1(nbuf, tid);  // overlaps others' compute
        compute_chunk(buf + f1off, buf + f2off, acc);

        __syncthreads();                     // readers of buf done; c1[cc+1] built
        if (cc + 2 < NCHUNK) {
            stage_chunk(f1base + (size_t)(cc + 2) * chunk_gstride,
                        f2base + (size_t)(cc + 2) * chunk_gstride,
                        buf, rlo, nrows, tid);
            cp_commit();
        }
    }

    // ---- epilogue: rows dj = djp + 2k ----
    const float inv = 1.0f / 64.0f;
    const int di = di0 + dil;
    const int h  = h0 + hl;
    const int nk = (djp == 0) ? 11 : 10;   // dj=20 only exists for djp==0
    for (int k = 0; k < nk; k++) {
        const int d = di * KS_ + djp + 2 * k;
        float* o = out + (((size_t)b * (KS_ * KS_) + d) * H_ + h) * W_ + w0;
        float v[8];
#pragma unroll
        for (int p = 0; p < 4; p++) {
            float2 f = *reinterpret_cast<float2*>(&acc[k][p]);
            v[2 * p]     = f.x * inv;
            v[2 * p + 1] = f.y * inv;
        }
        *reinterpret_cast<float4*>(o)     = make_float4(v[0], v[1], v[2], v[3]);
        *reinterpret_cast<float4*>(o + 4) = make_float4(v[4], v[5], v[6], v[7]);
    }
}

extern "C" void kernel_launch(void* const* d_in, const int* in_sizes, int n_in,
                              void* d_out, int out_size) {
    const float* f1 = (const float*)d_in[0];
    const float* f2 = (const float*)d_in[1];
    float* out = (float*)d_out;

    cudaFuncSetAttribute(corr_kernel, cudaFuncAttributeMaxDynamicSharedMemorySize,
                         SMEM_BYTES);

    dim3 grid(KS_ / DIB, H_ / HB, B_);   // (7, 64, 4) = 1792 CTAs
    corr_kernel<<<grid, NTHREADS, SMEM_BYTES>>>(f1, f2, out);
}

// round 11
// speedup vs baseline: 1.3549x; 1.3549x over previous
#include <cuda_runtime.h>
#include <cstdint>

// Correlation layer: out[b, di*21+dj, h, w] = (1/64) * sum_c f1[b,c,h,w] * f2pad[b,c,h+di,w+dj]
// B=4, C=64, H=W=128, MAX_DISP=10, KS=21 (441 displacements), fp32.

#define B_      4
#define C_      64
#define H_      128
#define W_      128
#define KS_     21
#define PAD_    10

#define HB   2      // h rows per CTA
#define DIB  3      // di values per CTA
#define CC   8      // channels per chunk
#define NCHUNK (C_ / CC)   // 8
#define PW   152    // padded f2 row width
#define NROW (HB + DIB - 1)  // 4

#define F2_STRIDE (CC * PW + 4)           // 1220 floats
#define F1A_SIZE  (HB * CC * W_)          // 2048 floats, rows [h][c][128]
#define OFF_F1B   F1A_SIZE                // shifted f1 copy: f1B[w] = row[w+1]
#define F1B_SIZE  (F1A_SIZE + 4)          // 2052 (pad)
#define OFF_C0    (OFF_F1B + F1B_SIZE)    // 4100 floats (16400 B, 16B-aligned)
#define F2_USED   (NROW * F2_STRIDE)      // 4880 floats
#define BUF_FLOATS (OFF_C0 + F2_USED + 12) // 8992 floats
#define SMEM_BYTES (2 * BUF_FLOATS * 4)    // 71936 B per CTA (2 CTAs/SM)

#define NTHREADS 192   // 6 warps = 2 hl * 3 dil; lanes = 16 wg * 2 djp

// ---------------- cp.async helpers ----------------
__device__ __forceinline__ void cp_async16(float* smem_dst, const float* gsrc) {
    uint32_t s = (uint32_t)__cvta_generic_to_shared(smem_dst);
    asm volatile("cp.async.cg.shared.global [%0], [%1], 16;\n" :: "r"(s), "l"(gsrc));
}
__device__ __forceinline__ void cp_async8(float* smem_dst, const float* gsrc) {
    uint32_t s = (uint32_t)__cvta_generic_to_shared(smem_dst);
    asm volatile("cp.async.ca.shared.global [%0], [%1], 8;\n" :: "r"(s), "l"(gsrc));
}
__device__ __forceinline__ void cp_commit() {
    asm volatile("cp.async.commit_group;\n" ::: "memory");
}
template <int N>
__device__ __forceinline__ void cp_wait() {
    asm volatile("cp.async.wait_group %0;\n" :: "n"(N) : "memory");
}

// packed f32x2 fma: d = a*b + c on both 32-bit halves
__device__ __forceinline__ unsigned long long fma_x2(unsigned long long a,
                                                     unsigned long long b,
                                                     unsigned long long c) {
    unsigned long long d;
    asm("fma.rn.f32x2 %0, %1, %2, %3;" : "=l"(d) : "l"(a), "l"(b), "l"(c));
    return d;
}

// ---------------- inner compute ----------------
// Identical instruction stream for both parities:
//   acc[k][2pc+p] += fa2[p] * fb2[k+p]
// djp=0: fa from aligned f1A -> dj = 2k (k=0..10), w = pb+2p,+1
// djp=1: fa from shifted f1B -> dj = 2k-1 (k=0 junk), w = pb+2p+1,+2
// Pieces pc=0,1 give pb = 4wg and 64+4wg. All LDS.128 lane addresses are
// 16B-stride contiguous (conflict-free); fb is parity-shared (broadcast pairs).
__device__ __forceinline__ void compute_chunk(const float* __restrict__ f1p,
                                              const float* __restrict__ f2p,
                                              int pb0,
                                              unsigned long long (&acc)[11][4]) {
#pragma unroll
    for (int pc = 0; pc < 2; pc++) {
        const int pb = pb0 + pc * 64;
#pragma unroll
        for (int c = 0; c < CC; c++) {
            ulonglong2 fav = *reinterpret_cast<const ulonglong2*>(f1p + c * W_ + pb);
            unsigned long long fa2[2] = {fav.x, fav.y};
            const ulonglong2* fbv = reinterpret_cast<const ulonglong2*>(f2p + c * PW + pb);
            unsigned long long fb2[12];
#pragma unroll
            for (int i = 0; i < 6; i++) {
                ulonglong2 t = fbv[i];
                fb2[2 * i] = t.x; fb2[2 * i + 1] = t.y;
            }
#pragma unroll
            for (int k = 0; k < 11; k++) {
#pragma unroll
                for (int p = 0; p < 2; p++)
                    acc[k][2 * pc + p] = fma_x2(fa2[p], fb2[k + p], acc[k][2 * pc + p]);
            }
        }
    }
}

// ---------------- staging (cp.async, gmem -> smem) ----------------
__device__ __forceinline__ void stage_chunk(const float* __restrict__ f1base,
                                            const float* __restrict__ f2base,
                                            float* buf,
                                            int rlo, int nrows, int tid) {
    // f1A: 512 float4; idx = hc*32 + w4, hc = h*8+c
    {
        const int w4 = tid & 31;
        int hc = tid >> 5;                  // advances by 6
        float* dst0 = buf + w4 * 4;
        const float* src0 = f1base + w4 * 4;
#pragma unroll
        for (int j = 0; j < 3; j++) {
            if (hc < HB * CC) {
                int h = hc >> 3, c = hc & 7;
                cp_async16(dst0 + hc * W_, src0 + c * (H_ * W_) + h * W_);
            }
            hc += 6;
        }
    }
    // c0: interior x in [10,138) via 8B; items (r*8+c)*64 + x2
    {
        const int x2 = tid & 63;
        int rc = tid >> 6;                  // advances by 3
        const int rcmax = nrows * 8;
        float* c0 = buf + OFF_C0 + rlo * F2_STRIDE + PAD_ + x2 * 2;
        const float* src0 = f2base + rlo * W_ + x2 * 2;
#pragma unroll
        for (int j = 0; j < 11; j++) {
            if (rc < rcmax) {
                int r = rc >> 3, c = rc & 7;
                cp_async8(c0 + r * F2_STRIDE + c * PW,
                          src0 + c * (H_ * W_) + r * W_);
            }
            rc += 3;
        }
    }
}

// ---------------- f1B build (smem -> smem 1-float shift) ----------------
// f1B[i] = f1A[i+1]; guarded at the very end (no cross-region race).
__device__ __forceinline__ void build_f1b(float* buf, int tid) {
    const float* a0 = buf;
    float* b0 = buf + OFF_F1B;
#pragma unroll
    for (int j = 0; j < 3; j++) {                 // ceil(512/192)
        int i4 = (tid + j * NTHREADS) * 4;
        if (i4 < F1A_SIZE) {
            float4 v = *reinterpret_cast<const float4*>(a0 + i4);
            float nxt = (i4 + 4 < F1A_SIZE) ? a0[i4 + 4] : 0.f;
            *reinterpret_cast<float4*>(b0 + i4) = make_float4(v.y, v.z, v.w, nxt);
        }
    }
}

extern __shared__ float smem[];

__global__ __launch_bounds__(NTHREADS, 2)
void corr_kernel(const float* __restrict__ f1g,
                 const float* __restrict__ f2g,
                 float* __restrict__ out) {
    const int tid  = threadIdx.x;
    const int warp = tid >> 5;
    const int lane = tid & 31;
    const int hl   = warp & 1;      // h row (warp-uniform)
    const int dil  = warp >> 1;     // local di (warp-uniform)
    const int wg   = lane >> 1;     // w tile
    const int djp  = lane & 1;      // dj parity
    const int pb0  = wg * 4;        // piece-0 base within row

    const int b   = blockIdx.z;
    const int h0  = blockIdx.y * HB;
    const int di0 = blockIdx.x * DIB;
    const int r0  = h0 + di0 - PAD_;

    int rlo = (r0 < 0) ? -r0 : 0;
    int rhi = (r0 + NROW > H_) ? (H_ - r0) : NROW;
    if (rhi < rlo) { rlo = 0; rhi = 0; }
    const int nrows = rhi - rlo;

    float* buf0 = smem;
    float* buf1 = smem + BUF_FLOATS;

    // one-time zero of f1B + c0 regions in both buffers
    {
        float4 z = make_float4(0.f, 0.f, 0.f, 0.f);
        float4* z0 = reinterpret_cast<float4*>(buf0 + OFF_F1B);
        float4* z1 = reinterpret_cast<float4*>(buf1 + OFF_F1B);
        const int n4 = (BUF_FLOATS - OFF_F1B) / 4;
        for (int i = tid; i < n4; i += NTHREADS) { z0[i] = z; z1[i] = z; }
    }
    __syncthreads();

    const float* f1base = f1g + ((size_t)b * C_ * H_ + h0) * W_;
    const float* f2base = f2g + ((size_t)b * C_ * H_ + r0) * W_;
    const int chunk_gstride = CC * H_ * W_;

    stage_chunk(f1base, f2base, buf0, rlo, nrows, tid);
    cp_commit();
    stage_chunk(f1base + chunk_gstride, f2base + chunk_gstride, buf1, rlo, nrows, tid);
    cp_commit();

    // prologue: chunk 0 staged -> build its f1B
    cp_wait<1>();
    __syncthreads();
    build_f1b(buf0, tid);

    unsigned long long acc[11][4];
#pragma unroll
    for (int k = 0; k < 11; k++)
#pragma unroll
        for (int p = 0; p < 4; p++) acc[k][p] = 0ull;

    const int f1off = djp * OFF_F1B + hl * (CC * W_);
    const int f2off = OFF_C0 + (hl + dil) * F2_STRIDE;

    for (int cc = 0; cc < NCHUNK; cc++) {
        float* buf  = (cc & 1) ? buf1 : buf0;
        float* nbuf = (cc & 1) ? buf0 : buf1;

        if (cc < NCHUNK - 1) cp_wait<0>();
        __syncthreads();                     // c0/f1A[cc+1] + f1B[cc] visible

        if (cc + 1 < NCHUNK) build_f1b(nbuf, tid);   // overlaps compute
        compute_chunk(buf + f1off, buf + f2off, pb0, acc);

        __syncthreads();                     // readers done; f1B[cc+1] built
        if (cc + 2 < NCHUNK) {
            stage_chunk(f1base + (size_t)(cc + 2) * chunk_gstride,
                        f2base + (size_t)(cc + 2) * chunk_gstride,
                        buf, rlo, nrows, tid);
            cp_commit();
        }
    }

    // ---- epilogue ----
    const float inv = 1.0f / 64.0f;
    const int di = di0 + dil;
    const int h  = h0 + hl;
    float* ob = out + (((size_t)b * (KS_ * KS_) + di * KS_) * H_ + h) * W_;

    if (djp == 0) {
        // dj = 2k, w = pb+2p..pb+2p+1 -> two aligned STG.128 per row
        for (int k = 0; k < 11; k++) {
            float* o = ob + (size_t)(2 * k) * (H_ * W_);
#pragma unroll
            for (int pc = 0; pc < 2; pc++) {
                float2 f0 = *reinterpret_cast<float2*>(&acc[k][2 * pc]);
                float2 f1v = *reinterpret_cast<float2*>(&acc[k][2 * pc + 1]);
                *reinterpret_cast<float4*>(o + pb0 + pc * 64) =
                    make_float4(f0.x * inv, f0.y * inv, f1v.x * inv, f1v.y * inv);
            }
        }
    } else {
        // dj = 2k-1 (k=1..10), w = pb+1..pb+4; mask spurious w=128
        for (int k = 1; k < 11; k++) {
            float* o = ob + (size_t)(2 * k - 1) * (H_ * W_);
#pragma unroll
            for (int pc = 0; pc < 2; pc++) {
                const int pb = pb0 + pc * 64;
                float2 f0 = *reinterpret_cast<float2*>(&acc[k][2 * pc]);
                float2 f1v = *reinterpret_cast<float2*>(&acc[k][2 * pc + 1]);
                o[pb + 1] = f0.x * inv;
                *reinterpret_cast<float2*>(o + pb + 2) =
                    make_float2(f0.y * inv, f1v.x * inv);
                if (pb + 4 < W_) o[pb + 4] = f1v.y * inv;
            }
        }
    }
}

// ---- fixup: odd-dj outputs at w=0 (shifted tiles skip them) ----
// out[b, di*21+dj, h, 0] for dj odd: dj<10 -> 0 (padding); dj=2t+11 ->
// (1/64) * sum_c f1[b,c,h,0] * f2[b,c,h+di-10, 2t+1]   (0 if row OOB).
__global__ void corr_fixup(const float* __restrict__ f1g,
                           const float* __restrict__ f2g,
                           float* __restrict__ out) {
    const int di = blockIdx.x;
    const int b  = blockIdx.y;
    const int h  = threadIdx.x;
    const int h2 = h + di - PAD_;
    const bool valid = (h2 >= 0) && (h2 < H_);

    float acc5[5] = {0.f, 0.f, 0.f, 0.f, 0.f};
    if (valid) {
        const float* f1p = f1g + ((size_t)b * C_ * H_ + h) * W_;
        const float* f2p = f2g + ((size_t)b * C_ * H_ + h2) * W_;
        for (int c = 0; c < C_; c++) {
            float a = f1p[c * (H_ * W_)];
            const float* fr = f2p + c * (H_ * W_);
#pragma unroll
            for (int t = 0; t < 5; t++) acc5[t] += a * fr[2 * t + 1];
        }
    }
    const float inv = 1.0f / 64.0f;
    float* ob = out + (((size_t)b * (KS_ * KS_) + di * KS_) * H_ + h) * W_;
#pragma unroll
    for (int t = 0; t < 5; t++) {
        ob[(size_t)(2 * t + 1) * (H_ * W_)] = 0.f;                       // dj=1..9 odd
        ob[(size_t)(2 * t + 11) * (H_ * W_)] = valid ? acc5[t] * inv : 0.f; // dj=11..19
    }
}

extern "C" void kernel_launch(void* const* d_in, const int* in_sizes, int n_in,
                              void* d_out, int out_size) {
    const float* f1 = (const float*)d_in[0];
    const float* f2 = (const float*)d_in[1];
    float* out = (float*)d_out;

    cudaFuncSetAttribute(corr_kernel, cudaFuncAttributeMaxDynamicSharedMemorySize,
                         SMEM_BYTES);

    dim3 grid(KS_ / DIB, H_ / HB, B_);   // (7, 64, 4) = 1792 CTAs
    corr_kernel<<<grid, NTHREADS, SMEM_BYTES>>>(f1, f2, out);

    dim3 fgrid(KS_, B_);                 // (21, 4), 128 threads = h
    corr_fixup<<<fgrid, H_>>>(f1, f2, out);
}

// round 12
// speedup vs baseline: 1.6973x; 1.2527x over previous
#include <cuda_runtime.h>
#include <cstdint>

// Correlation layer: out[b, di*21+dj, h, w] = (1/64) * sum_c f1[b,c,h,w] * f2pad[b,c,h+di,w+dj]
// B=4, C=64, H=W=128, MAX_DISP=10, KS=21 (441 displacements), fp32.

#define B_      4
#define C_      64
#define H_      128
#define W_      128
#define KS_     21
#define PAD_    10

#define HB   2
#define DIB  3
#define CC   8
#define NCHUNK (C_ / CC)   // 8
#define PW   152
#define NROW (HB + DIB - 1)  // 4

#define F2_STRIDE (CC * PW + 4)           // 1220 floats
#define F1A_SIZE  (HB * CC * W_)          // 2048 floats
#define OFF_F1B   (F1A_SIZE + 16)         // 2064: 8256 B ≡ 64 mod 128 -> parity
                                          // fa loads hit disjoint bank quads
#define F1B_SIZE  (F1A_SIZE + 4)          // 2052
#define OFF_C0    (OFF_F1B + F1B_SIZE)    // 4116 floats (16B-aligned)
#define F2_USED   (NROW * F2_STRIDE)      // 4880
#define BUF_FLOATS (OFF_C0 + F2_USED + 12) // 9008 floats = 36032 B
#define SMEM_BYTES (3 * BUF_FLOATS * 4)    // 108096 B per CTA (2 CTAs/SM)

#define NTHREADS 192   // 6 warps = 2 hl * 3 dil; lanes = 16 wg * 2 djp

// ---------------- cp.async helpers ----------------
__device__ __forceinline__ void cp_async16(float* smem_dst, const float* gsrc) {
    uint32_t s = (uint32_t)__cvta_generic_to_shared(smem_dst);
    asm volatile("cp.async.cg.shared.global [%0], [%1], 16;\n" :: "r"(s), "l"(gsrc));
}
__device__ __forceinline__ void cp_async8(float* smem_dst, const float* gsrc) {
    uint32_t s = (uint32_t)__cvta_generic_to_shared(smem_dst);
    asm volatile("cp.async.ca.shared.global [%0], [%1], 8;\n" :: "r"(s), "l"(gsrc));
}
__device__ __forceinline__ void cp_commit() {
    asm volatile("cp.async.commit_group;\n" ::: "memory");
}
template <int N>
__device__ __forceinline__ void cp_wait() {
    asm volatile("cp.async.wait_group %0;\n" :: "n"(N) : "memory");
}

// packed f32x2 fma
__device__ __forceinline__ unsigned long long fma_x2(unsigned long long a,
                                                     unsigned long long b,
                                                     unsigned long long c) {
    unsigned long long d;
    asm("fma.rn.f32x2 %0, %1, %2, %3;" : "=l"(d) : "l"(a), "l"(b), "l"(c));
    return d;
}

// ---------------- inner compute ----------------
// Identical instruction stream for both parities:
//   acc[k][2pc+p] += fa2[p] * fb2[k+p]
// djp=0: fa from f1A -> dj = 2k (k=0..10), w = pb+2p,+1
// djp=1: fa from shifted f1B -> dj = 2k-1 (k=0 junk), w = pb+2p+1,+2
// All LDS.128 lane address sets are conflict-free; fb is parity-shared.
__device__ __forceinline__ void compute_chunk(const float* __restrict__ f1p,
                                              const float* __restrict__ f2p,
                                              int pb0,
                                              unsigned long long (&acc)[11][4]) {
#pragma unroll
    for (int pc = 0; pc < 2; pc++) {
        const int pb = pb0 + pc * 64;
#pragma unroll
        for (int c = 0; c < CC; c++) {
            ulonglong2 fav = *reinterpret_cast<const ulonglong2*>(f1p + c * W_ + pb);
            unsigned long long fa2[2] = {fav.x, fav.y};
            const ulonglong2* fbv = reinterpret_cast<const ulonglong2*>(f2p + c * PW + pb);
            unsigned long long fb2[12];
#pragma unroll
            for (int i = 0; i < 6; i++) {
                ulonglong2 t = fbv[i];
                fb2[2 * i] = t.x; fb2[2 * i + 1] = t.y;
            }
#pragma unroll
            for (int k = 0; k < 11; k++) {
#pragma unroll
                for (int p = 0; p < 2; p++)
                    acc[k][2 * pc + p] = fma_x2(fa2[p], fb2[k + p], acc[k][2 * pc + p]);
            }
        }
    }
}

// ---------------- staging (cp.async, gmem -> smem) ----------------
__device__ __forceinline__ void stage_chunk(const float* __restrict__ f1base,
                                            const float* __restrict__ f2base,
                                            float* buf,
                                            int rlo, int nrows, int tid) {
    {
        const int w4 = tid & 31;
        int hc = tid >> 5;                  // advances by 6
        float* dst0 = buf + w4 * 4;
        const float* src0 = f1base + w4 * 4;
#pragma unroll
        for (int j = 0; j < 3; j++) {
            if (hc < HB * CC) {
                int h = hc >> 3, c = hc & 7;
                cp_async16(dst0 + hc * W_, src0 + c * (H_ * W_) + h * W_);
            }
            hc += 6;
        }
    }
    {
        const int x2 = tid & 63;
        int rc = tid >> 6;                  // advances by 3
        const int rcmax = nrows * 8;
        float* c0 = buf + OFF_C0 + rlo * F2_STRIDE + PAD_ + x2 * 2;
        const float* src0 = f2base + rlo * W_ + x2 * 2;
#pragma unroll
        for (int j = 0; j < 11; j++) {
            if (rc < rcmax) {
                int r = rc >> 3, c = rc & 7;
                cp_async8(c0 + r * F2_STRIDE + c * PW,
                          src0 + c * (H_ * W_) + r * W_);
            }
            rc += 3;
        }
    }
}

// ---------------- f1B build (smem 1-float shift of f1A) ----------------
__device__ __forceinline__ void build_f1b(float* buf, int tid) {
    const float* a0 = buf;
    float* b0 = buf + OFF_F1B;
#pragma unroll
    for (int j = 0; j < 3; j++) {                 // ceil(512/192)
        int i4 = (tid + j * NTHREADS) * 4;
        if (i4 < F1A_SIZE) {
            float4 v = *reinterpret_cast<const float4*>(a0 + i4);
            float nxt = (i4 + 4 < F1A_SIZE) ? a0[i4 + 4] : 0.f;
            *reinterpret_cast<float4*>(b0 + i4) = make_float4(v.y, v.z, v.w, nxt);
        }
    }
}

extern __shared__ float smem[];

__global__ __launch_bounds__(NTHREADS, 2)
void corr_kernel(const float* __restrict__ f1g,
                 const float* __restrict__ f2g,
                 float* __restrict__ out) {
    const int tid  = threadIdx.x;
    const int warp = tid >> 5;
    const int lane = tid & 31;
    const int hl   = warp & 1;
    const int dil  = warp >> 1;
    const int wg   = lane >> 1;
    const int djp  = lane & 1;
    const int pb0  = wg * 4;

    const int b   = blockIdx.z;
    const int h0  = blockIdx.y * HB;
    const int di0 = blockIdx.x * DIB;
    const int r0  = h0 + di0 - PAD_;

    int rlo = (r0 < 0) ? -r0 : 0;
    int rhi = (r0 + NROW > H_) ? (H_ - r0) : NROW;
    if (rhi < rlo) { rlo = 0; rhi = 0; }
    const int nrows = rhi - rlo;

    float* bufA = smem;
    float* bufB = smem + BUF_FLOATS;
    float* bufC = smem + 2 * BUF_FLOATS;

    // one-time zero of f1B + c0 regions in all three buffers
    {
        float4 z = make_float4(0.f, 0.f, 0.f, 0.f);
        const int n4 = (BUF_FLOATS - OFF_F1B) / 4;
        float4* zA = reinterpret_cast<float4*>(bufA + OFF_F1B);
        float4* zB = reinterpret_cast<float4*>(bufB + OFF_F1B);
        float4* zC = reinterpret_cast<float4*>(bufC + OFF_F1B);
        for (int i = tid; i < n4; i += NTHREADS) { zA[i] = z; zB[i] = z; zC[i] = z; }
    }
    __syncthreads();

    const float* f1base = f1g + ((size_t)b * C_ * H_ + h0) * W_;
    const float* f2base = f2g + ((size_t)b * C_ * H_ + r0) * W_;
    const int chunk_gstride = CC * H_ * W_;

    // prologue: stage chunks 0,1; build f1B for chunk 0
    stage_chunk(f1base, f2base, bufA, rlo, nrows, tid);
    cp_commit();
    stage_chunk(f1base + chunk_gstride, f2base + chunk_gstride, bufB, rlo, nrows, tid);
    cp_commit();
    cp_wait<1>();
    __syncthreads();
    build_f1b(bufA, tid);

    unsigned long long acc[11][4];
#pragma unroll
    for (int k = 0; k < 11; k++)
#pragma unroll
        for (int p = 0; p < 4; p++) acc[k][p] = 0ull;
    float accfix = 0.f;   // fused fixup accumulator (djp==1 && wg<5)

    const int f1off = djp * OFF_F1B + hl * (CC * W_);
    const int f2off = OFF_C0 + (hl + dil) * F2_STRIDE;
    const bool fixlane = (djp == 1) && (wg < 5);

    float* p0 = bufA;   // compute chunk cc
    float* p1 = bufB;   // build f1B for chunk cc+1
    float* p2 = bufC;   // stage chunk cc+2

    for (int cc = 0; cc < NCHUNK; cc++) {
        cp_wait<0>();          // chunk cc+1 staging (committed last iter) done
        __syncthreads();       // staging + f1B[cc] visible; p2's old readers done

        if (cc + 2 < NCHUNK) {
            stage_chunk(f1base + (size_t)(cc + 2) * chunk_gstride,
                        f2base + (size_t)(cc + 2) * chunk_gstride,
                        p2, rlo, nrows, tid);
            cp_commit();
        }
        if (cc + 1 < NCHUNK) build_f1b(p1, tid);

        compute_chunk(p0 + f1off, p0 + f2off, pb0, acc);

        // fused fixup: out[b, di*21+(2t+11), h, 0] needs
        // sum_c f1[b,c,h,0] * c0row[2t+11]; zeroed OOB rows make the guard free.
        if (fixlane) {
            const float* fa0 = p0 + hl * (CC * W_);          // f1A (unshifted)
            const float* fb0 = p0 + f2off + 11 + 2 * wg;     // t = wg
#pragma unroll
            for (int c = 0; c < CC; c++)
                accfix = fmaf(fa0[c * W_], fb0[c * PW], accfix);
        }

        float* t = p0; p0 = p1; p1 = p2; p2 = t;   // rotate
    }

    // ---- epilogue ----
    const float inv = 1.0f / 64.0f;
    const int di = di0 + dil;
    const int h  = h0 + hl;
    float* ob = out + (((size_t)b * (KS_ * KS_) + di * KS_) * H_ + h) * W_;

    if (djp == 0) {
        for (int k = 0; k < 11; k++) {
            float* o = ob + (size_t)(2 * k) * (H_ * W_);
#pragma unroll
            for (int pc = 0; pc < 2; pc++) {
                float2 f0 = *reinterpret_cast<float2*>(&acc[k][2 * pc]);
                float2 f1v = *reinterpret_cast<float2*>(&acc[k][2 * pc + 1]);
                *reinterpret_cast<float4*>(o + pb0 + pc * 64) =
                    make_float4(f0.x * inv, f0.y * inv, f1v.x * inv, f1v.y * inv);
            }
        }
    } else {
        for (int k = 1; k < 11; k++) {
            float* o = ob + (size_t)(2 * k - 1) * (H_ * W_);
#pragma unroll
            for (int pc = 0; pc < 2; pc++) {
                const int pb = pb0 + pc * 64;
                float2 f0 = *reinterpret_cast<float2*>(&acc[k][2 * pc]);
                float2 f1v = *reinterpret_cast<float2*>(&acc[k][2 * pc + 1]);
                o[pb + 1] = f0.x * inv;
                *reinterpret_cast<float2*>(o + pb + 2) =
                    make_float2(f0.y * inv, f1v.x * inv);
                if (pb + 4 < W_) o[pb + 4] = f1v.y * inv;
            }
        }
        if (wg < 5) {
            // w=0, odd dj: dj=2wg+1 (<10) is padding-zero; dj=2wg+11 from accfix
            ob[(size_t)(2 * wg + 1) * (H_ * W_)] = 0.f;
            ob[(size_t)(2 * wg + 11) * (H_ * W_)] = accfix * inv;
        }
    }
}

extern "C" void kernel_launch(void* const* d_in, const int* in_sizes, int n_in,
                              void* d_out, int out_size) {
    const float* f1 = (const float*)d_in[0];
    const float* f2 = (const float*)d_in[1];
    float* out = (float*)d_out;

    cudaFuncSetAttribute(corr_kernel, cudaFuncAttributeMaxDynamicSharedMemorySize,
                         SMEM_BYTES);

    dim3 grid(KS_ / DIB, H_ / HB, B_);   // (7, 64, 4) = 1792 CTAs
    corr_kernel<<<grid, NTHREADS, SMEM_BYTES>>>(f1, f2, out);
}